// round 17
// baseline (speedup 1.0000x reference)
#include <cuda_runtime.h>
#include <cfloat>

// Problem shapes are FIXED by the reference (CAPACITY = 2^21, SIZE = 2^20).
#define CAP   2097152
#define NSAMP 1048576

// 1-BASED sum tree, PARTIAL: ONLY levels 13..18 are materialized
// (node q at g_tree[q], children 2q/2q+1; level L at [2^L, 2^(L+1))).
// Levels 19/20/leaves are reconstructed from pri in registers at traversal
// time; levels 0..11 are replaced by the level-12 prefix (g_pref).
// g_tree[1] holds the total.
__device__ float g_tree[1 << 19];
// Exclusive prefix of the 4096 level-12 node sums; g_pref[4096] = sentinel.
__device__ float g_pref[4097];

// ---------------------------------------------------------------------------
// Build levels 18..13: 256 thr/block, 8 leaves/thread (two float4 loads).
// Levels 20/19 computed in registers but NOT stored (traversal rebuilds
// them from pri). Level 18 scalar store, 17..13 via warp shuffles.
// No barriers, no atomics. All sums adjacent pairs -> bit-identical to
// jnp reshape(-1,2).sum.
// ---------------------------------------------------------------------------
__global__ __launch_bounds__(256) void build_tree(const float* __restrict__ pri) {
    const int t   = threadIdx.x;
    const int b   = blockIdx.x;
    const int lid = t & 31;
    const int w   = t >> 5;
    const int g   = b * 256 + t;          // 0 .. 2^18-1

    const float4* p4 = reinterpret_cast<const float4*>(pri);
    const float4 a = p4[2 * g];
    const float4 c = p4[2 * g + 1];

    const float s0 = a.x + a.y, s1 = a.z + a.w;
    const float s2 = c.x + c.y, s3 = c.z + c.w;
    const float t0 = s0 + s1,  t1 = s2 + s3;

    float val = t0 + t1;
    g_tree[(1 << 18) + g] = val;          // level 18

    const int wg = b * 8 + w;             // global warp id = level-13 node id
    #pragma unroll
    for (int L = 17, n = 16; L >= 13; L--, n >>= 1) {
        const float pair = val + __shfl_down_sync(0xffffffffu, val, 1);
        val = __shfl_sync(0xffffffffu, pair, 2 * lid);
        if (lid < n) g_tree[(1 << L) + wg * n + lid] = val;
    }
}

// ---------------------------------------------------------------------------
// Level-12 prefix: one block, 256 threads. Level-12 node = sum of its
// level-13 pair (adjacent-pair order). Exclusive block scan ->
// g_pref[0..4095]; sentinel at [4096]; total -> g_tree[1].
// ---------------------------------------------------------------------------
__global__ __launch_bounds__(256) void prefix12() {
    const int t   = threadIdx.x;
    const int lid = t & 31;
    const int w   = t >> 5;

    const float4* l13 = reinterpret_cast<const float4*>(&g_tree[1 << 13]);
    float loc[16];
    float run = 0.0f;
    #pragma unroll
    for (int k = 0; k < 8; k++) {
        const float4 v = l13[t * 8 + k];
        loc[2 * k]     = run;  run += v.x + v.y;
        loc[2 * k + 1] = run;  run += v.z + v.w;
    }

    float x = run;
    #pragma unroll
    for (int o = 1; o < 32; o <<= 1) {
        const float y = __shfl_up_sync(0xffffffffu, x, o);
        if (lid >= o) x += y;
    }
    __shared__ float wsum[8], wbase[8];
    if (lid == 31) wsum[w] = x;
    __syncthreads();
    if (t == 0) {
        float acc = 0.0f;
        #pragma unroll
        for (int i = 0; i < 8; i++) { wbase[i] = acc; acc += wsum[i]; }
        g_tree[1] = acc;                  // total
        g_pref[4096] = FLT_MAX;           // sentinel
    }
    __syncthreads();

    const float base = wbase[w] + (x - run);
    #pragma unroll
    for (int k = 0; k < 16; k++)
        g_pref[t * 16 + k] = base + loc[k];
}

// ---------------------------------------------------------------------------
// Traversal: level-12 jump-start (guess + local scan on 16 KB L1-resident
// prefix), 6 dependent tree loads (levels 13..18), then the level-18 node's
// 8 leaves arrive as two float4 loads from pri and levels 19/20/leaf are
// resolved in registers with bit-identical pair sums. Blocked ILP=4.
// Output float32 (validator dtype); values < 2^21 exact.
// ---------------------------------------------------------------------------
#define TRAV_BLK 256
#define ILP      4

__global__ __launch_bounds__(TRAV_BLK) void traverse(const float* __restrict__ uni,
                                                     const float* __restrict__ pri,
                                                     float* __restrict__ out) {
    const int j = blockIdx.x * TRAV_BLK + threadIdx.x;   // 0 .. NSAMP/4-1

    const float total = __ldg(&g_tree[1]);
    const float step  = total / (float)NSAMP;
    const float inv12 = 4096.0f / total;
    const float4 u = reinterpret_cast<const float4*>(uni)[j];

    float s[ILP];
    int   idx[ILP];
    s[0] = (u.x + (float)(4 * j + 0)) * step;
    s[1] = (u.y + (float)(4 * j + 1)) * step;
    s[2] = (u.z + (float)(4 * j + 2)) * step;
    s[3] = (u.w + (float)(4 * j + 3)) * step;

    // jump-start: locate level-12 node (pref[q] < s <= pref[q+1])
    #pragma unroll
    for (int k = 0; k < ILP; k++) {
        int q = (int)(s[k] * inv12);
        q = max(0, min(4095, q));
        while (q > 0 && __ldg(&g_pref[q]) >= s[k]) q--;
        while (__ldg(&g_pref[q + 1]) < s[k]) q++;    // sentinel caps at 4095
        s[k] -= __ldg(&g_pref[q]);
        idx[k] = 4096 + q;                            // 1-based node, level 12
    }

    // descend levels 12 -> 18 (6 dependent loads, levels 13..18)
    #pragma unroll
    for (int d = 12; d < 18; d++) {
        #pragma unroll
        for (int k = 0; k < ILP; k++) {
            const int l = 2 * idx[k];
            const float v = __ldg(&g_tree[l]);
            if (s[k] <= v) { idx[k] = l; } else { idx[k] = l + 1; s[k] -= v; }
        }
    }

    // levels 19/20/leaf in registers from the node's 8 leaves (2x float4)
    const float4* p4 = reinterpret_cast<const float4*>(pri);
    float4 A[ILP], B[ILP];
    int base[ILP];
    #pragma unroll
    for (int k = 0; k < ILP; k++) {
        base[k] = (idx[k] - (1 << 18)) * 8;           // first leaf (0-based)
        A[k] = __ldg(&p4[base[k] >> 2]);              // leaves 0..3
        B[k] = __ldg(&p4[(base[k] >> 2) + 1]);        // leaves 4..7
    }

    float4 r;
    float* rp = &r.x;
    #pragma unroll
    for (int k = 0; k < ILP; k++) {
        float sv = s[k];
        // level 19: left child value = (x0+x1)+(x2+x3)
        const float l19 = (A[k].x + A[k].y) + (A[k].z + A[k].w);
        const bool r19 = sv > l19;
        if (r19) sv -= l19;
        const float4 sel = r19 ? B[k] : A[k];
        // level 20: left child value = sel.x + sel.y
        const float l20 = sel.x + sel.y;
        const bool r20 = sv > l20;
        if (r20) sv -= l20;
        const float leftleaf = r20 ? sel.z : sel.x;
        // leaf step
        const bool rl = sv > leftleaf;
        rp[k] = (float)(base[k] + (r19 ? 4 : 0) + (r20 ? 2 : 0) + (rl ? 1 : 0));
    }
    reinterpret_cast<float4*>(out)[j] = r;
}

extern "C" void kernel_launch(void* const* d_in, const int* in_sizes, int n_in,
                              void* d_out, int out_size) {
    const float* pri = (const float*)d_in[0];
    const float* uni = (const float*)d_in[1];
    if (n_in >= 2 && in_sizes[1] == 2 * in_sizes[0]) {
        pri = (const float*)d_in[1];
        uni = (const float*)d_in[0];
    }

    build_tree<<<1024, 256>>>(pri);   // levels 18..13 only, barrier-free
    prefix12<<<1, 256>>>();           // level-12 prefix + total

    traverse<<<NSAMP / ILP / TRAV_BLK, TRAV_BLK>>>(uni, pri, (float*)d_out);
}